// round 7
// baseline (speedup 1.0000x reference)
#include <cuda_runtime.h>
#include <math.h>

// Problem constants
#define TT 2048
#define BB 4
#define II 1024
#define HH 1024
#define GG (4 * HH)  // 4096 gate rows

// ---------------- scratch (static device globals; no allocations) ----------
__device__ float g_pre[(size_t)TT * BB * GG];  // [8192][4096] x@W_in^T (128 MB)
__device__ float g_h[2][BB * HH];              // double-buffered hidden state
// 8 arrival counters on separate 128B L2 lines + one release word. Monotonic
// per launch; reset by gemm_pre block (0,0) inside the graph (replay-safe).
__device__ __align__(128) unsigned g_ctr[8 * 32];
__device__ unsigned g_go;

// packed fp32x2 FMA: d.lo += a.lo*b.lo ; d.hi += a.hi*b.hi (sm_100+)
__device__ __forceinline__ void ffma2(unsigned long long& d, unsigned long long a,
                                      unsigned long long b) {
    asm("fma.rn.f32x2 %0, %1, %2, %0;" : "+l"(d) : "l"(a), "l"(b));
}
__device__ __forceinline__ float ull_lo(unsigned long long v) {
    return __uint_as_float((unsigned)v);
}
__device__ __forceinline__ float ull_hi(unsigned long long v) {
    return __uint_as_float((unsigned)(v >> 32));
}

// ---------------- kernel 1: pre = x @ W_in^T  (M=8192, N=4096, K=1024) ------
// fp32x2-packed tiled GEMM: BM=128, BN=128, BK=16, 256 threads, 8x8
// tile/thread (acc packed along M: 4x8 ull = 32 FFMA2 per kk per thread).
// Block (0,0) additionally resets the recurrence scratch (replaces the old
// init_kernel; safe because lstm_rec runs in a later launch).
#define GBM 128
#define GBN 128
#define GBK 16

__global__ __launch_bounds__(256) void gemm_pre(const float* __restrict__ x,
                                                const float* __restrict__ Win) {
    __shared__ __align__(16) float As[GBK][GBM];
    __shared__ __align__(16) float Bs[GBK][GBN];
    const int tid = threadIdx.x;
    const int tx = tid & 15;        // 0..15  -> N (8 cols each)
    const int ty = tid >> 4;        // 0..15  -> M (8 rows each)
    const int mBase = blockIdx.y * GBM;
    const int nBase = blockIdx.x * GBN;

    // ---- inlined init (one block only): reset barrier state + h0 = 0 ----
    if (blockIdx.x == 0 && blockIdx.y == 0) {
        g_ctr[tid] = 0u;                      // 256 == 8*32 words exactly
        if (tid == 0) g_go = 0u;
#pragma unroll
        for (int i = 0; i < (2 * BB * HH) / 256; i++)
            ((float*)g_h)[i * 256 + tid] = 0.0f;
    }

    unsigned long long acc2[4][8];
#pragma unroll
    for (int i = 0; i < 4; i++)
#pragma unroll
        for (int j = 0; j < 8; j++) acc2[i][j] = 0ull;

    for (int k0 = 0; k0 < II; k0 += GBK) {
        // A tile: 128 rows x 16 k = 512 float4; B tile same shape
#pragma unroll
        for (int q = 0; q < 2; q++) {
            int id = tid * 2 + q;               // 0..511
            int m = id >> 2;
            int k4 = (id & 3) * 4;
            float4 v = *(const float4*)&x[(size_t)(mBase + m) * II + k0 + k4];
            As[k4 + 0][m] = v.x;
            As[k4 + 1][m] = v.y;
            As[k4 + 2][m] = v.z;
            As[k4 + 3][m] = v.w;
        }
#pragma unroll
        for (int q = 0; q < 2; q++) {
            int id = tid * 2 + q;               // 0..511
            int n = id >> 2;
            int k4 = (id & 3) * 4;
            float4 v = *(const float4*)&Win[(size_t)(nBase + n) * II + k0 + k4];
            Bs[k4 + 0][n] = v.x;
            Bs[k4 + 1][n] = v.y;
            Bs[k4 + 2][n] = v.z;
            Bs[k4 + 3][n] = v.w;
        }
        __syncthreads();

#pragma unroll
        for (int kk = 0; kk < GBK; kk++) {
            ulonglong2 t0 = *(const ulonglong2*)&As[kk][ty * 8];
            ulonglong2 t1 = *(const ulonglong2*)&As[kk][ty * 8 + 4];
            unsigned long long a2[4] = {t0.x, t0.y, t1.x, t1.y};
            float bq[8];
            *(float4*)&bq[0] = *(const float4*)&Bs[kk][tx * 8];
            *(float4*)&bq[4] = *(const float4*)&Bs[kk][tx * 8 + 4];
            unsigned long long bd[8];
#pragma unroll
            for (int j = 0; j < 8; j++) {
                unsigned bu = __float_as_uint(bq[j]);
                asm("mov.b64 %0, {%1, %1};" : "=l"(bd[j]) : "r"(bu));
            }
#pragma unroll
            for (int i = 0; i < 4; i++)
#pragma unroll
                for (int j = 0; j < 8; j++) ffma2(acc2[i][j], a2[i], bd[j]);
        }
        __syncthreads();
    }

#pragma unroll
    for (int i = 0; i < 4; i++) {
#pragma unroll
        for (int half = 0; half < 2; half++) {
            float4 vlo = make_float4(ull_lo(acc2[i][half * 4 + 0]), ull_lo(acc2[i][half * 4 + 1]),
                                     ull_lo(acc2[i][half * 4 + 2]), ull_lo(acc2[i][half * 4 + 3]));
            float4 vhi = make_float4(ull_hi(acc2[i][half * 4 + 0]), ull_hi(acc2[i][half * 4 + 1]),
                                     ull_hi(acc2[i][half * 4 + 2]), ull_hi(acc2[i][half * 4 + 3]));
            *(float4*)&g_pre[(size_t)(mBase + ty * 8 + 2 * i + 0) * GG + nBase + tx * 8 + half * 4] = vlo;
            *(float4*)&g_pre[(size_t)(mBase + ty * 8 + 2 * i + 1) * GG + nBase + tx * 8 + half * 4] = vhi;
        }
    }
}

// ---------------- kernel 2: persistent recurrence ---------------------------
// 128 CTAs x 256 threads (8 warps). CTA owns 8 hidden units (32 gate rows in
// smem, 128 KB). Warp w: gate = w>>1, K-half = w&1; 8 rows x 4 batches over
// K=512 with packed FFMA2, register transpose-reduce, warp-0 cell update
// (c-state in registers). Grid sync: 8-line atomic arrival + CTA0
// master-release broadcast word g_go.
#define NBLK 128
#define UPB 8
#define ROWS 32
#define RTH 256

__global__ __launch_bounds__(RTH) void lstm_rec(const float* __restrict__ Whh,
                                                float* __restrict__ out) {
    extern __shared__ float sm[];
    float* W_s = sm;                          // [32][1024] 128 KB
    float* h_s = W_s + ROWS * HH;             // [4][1024]   16 KB
    float* part_s = h_s + BB * HH;            // [2 khalf][4 gate][32]  1 KB

    const int tid = threadIdx.x;
    const int blk = blockIdx.x;
    const int warp = tid >> 5;
    const int lane = tid & 31;
    const int gate = warp >> 1;               // 0..3
    const int khalf = warp & 1;               // 0..1

    // Stage W: local row r = gate*8 + u  <-  Whh[gate*1024 + blk*8 + u]
    for (int id = tid; id < ROWS * (HH / 4); id += RTH) {
        int r = id / (HH / 4);
        int c4 = id % (HH / 4);
        int g = r >> 3, ul = r & 7;
        ((float4*)&W_s[r * HH])[c4] =
            ((const float4*)&Whh[(size_t)(g * HH + blk * UPB + ul) * HH])[c4];
    }
    __syncthreads();

    // warp0 persistent cell state: lane = u*4 + b
    const int u = lane >> 2, b = lane & 3;
    const int ug = blk * UPB + u;
    float c_val = 0.0f;

    const float* Wbase = &W_s[gate * UPB * HH + khalf * (HH / 2)];
    const float* hbase = &h_s[khalf * (HH / 2)];

    for (int t = 0; t < TT; t++) {
        // Prefetch this step's pre-activations (consumed ~2000 cyc later).
        float pre_r[4];
        if (warp == 0) {
#pragma unroll
            for (int g = 0; g < 4; g++)
                pre_r[g] = __ldcs(&g_pre[(size_t)(t * BB + b) * GG + g * HH + ug]);
        }

        // Stage h_t (buffer t&1) into smem; __ldcg bypasses stale L1.
        const float4* hsrc = (const float4*)g_h[t & 1];
        for (int i = tid; i < (BB * HH) / 4; i += RTH)
            ((float4*)h_s)[i] = __ldcg(&hsrc[i]);
        __syncthreads();

        // GEMV: 8 rows x 4 batches over K=512 (4 iterations of 128).
        unsigned long long acc[8][4];
#pragma unroll
        for (int j = 0; j < 8; j++)
#pragma unroll
            for (int bb = 0; bb < 4; bb++) acc[j][bb] = 0ull;

#pragma unroll
        for (int it = 0; it < 4; it++) {
            const int base = it * 128 + lane * 4;
            ulonglong2 hv[4];
#pragma unroll
            for (int bb = 0; bb < 4; bb++)
                hv[bb] = *(const ulonglong2*)&hbase[bb * HH + base];
#pragma unroll
            for (int j = 0; j < 8; j++) {
                ulonglong2 wv = *(const ulonglong2*)&Wbase[j * HH + base];
#pragma unroll
                for (int bb = 0; bb < 4; bb++) {
                    ffma2(acc[j][bb], wv.x, hv[bb].x);
                    ffma2(acc[j][bb], wv.y, hv[bb].y);
                }
            }
        }

        // Collapse packed accumulators -> 32 scalars (index = j*4 + bb = u*4+b)
        float a[32];
#pragma unroll
        for (int j = 0; j < 8; j++)
#pragma unroll
            for (int bb = 0; bb < 4; bb++)
                a[j * 4 + bb] = ull_lo(acc[j][bb]) + ull_hi(acc[j][bb]);

        // Register transpose-reduce: lane l ends with full sum of index l.
#pragma unroll
        for (int s = 16; s >= 1; s >>= 1) {
            const bool up = (lane & s) != 0;
#pragma unroll
            for (int k = 0; k < s; k++) {
                float sendv = up ? a[k] : a[k + s];
                float keepv = up ? a[k + s] : a[k];
                float got = __shfl_xor_sync(0xFFFFFFFFu, sendv, s);
                a[k] = keepv + got;
            }
        }
        part_s[(khalf * 4 + gate) * 32 + lane] = a[0];
        __syncthreads();

        // Cell update: warp 0, lane = u*4 + b. Sum the two K-half partials.
        if (tid < 32) {
            float gi = pre_r[0] + part_s[0 * 32 + lane] + part_s[4 * 32 + lane];
            float gf = pre_r[1] + part_s[1 * 32 + lane] + part_s[5 * 32 + lane];
            float gc = pre_r[2] + part_s[2 * 32 + lane] + part_s[6 * 32 + lane];
            float go = pre_r[3] + part_s[3 * 32 + lane] + part_s[7 * 32 + lane];
            float i_s = 1.0f / (1.0f + __expf(-gi));
            float f_s = 1.0f / (1.0f + __expf(-gf));
            float o_s = 1.0f / (1.0f + __expf(-go));
            float g_t = tanhf(gc);
            c_val = f_s * c_val + i_s * g_t;
            float h = o_s * tanhf(c_val);
            g_h[(t + 1) & 1][b * HH + ug] = h;                      // next step input
            out[(size_t)(t * BB + b) * HH + ug] = h;                // layer output
            if (t == TT - 1) {
                out[(size_t)TT * BB * HH + b * HH + ug] = h;            // h_T
                out[(size_t)TT * BB * HH + BB * HH + b * HH + ug] = c_val;  // c_T
            }
            __threadfence();  // warp-uniform MEMBAR: publish h before arrive
        }
        // NOTE: no __syncthreads here. Warp 0's fence already orders this
        // CTA's externally-visible state (h stores) before tid0's arrival;
        // warps 1-7 publish nothing after the part_s sync.

        // Grid barrier: arrival on 8 distributed counters; CTA0 aggregates and
        // broadcasts the release via g_go; everyone else polls one L2 line.
        if (tid == 0) {
            atomicAdd(&g_ctr[(blk & 7) * 32], 1u);
            const unsigned tgt = (unsigned)(t + 1);
            if (blk == 0) {
                const unsigned target = tgt * NBLK;
                volatile unsigned* vc = (volatile unsigned*)g_ctr;
                unsigned s;
                do {
                    s = vc[0 * 32] + vc[1 * 32] + vc[2 * 32] + vc[3 * 32] +
                        vc[4 * 32] + vc[5 * 32] + vc[6 * 32] + vc[7 * 32];
                } while (s < target);
                *((volatile unsigned*)&g_go) = tgt;
            } else {
                volatile unsigned* vg = (volatile unsigned*)&g_go;
                while (*vg < tgt) {
                }
            }
        }
        __syncthreads();
    }
}

// ---------------- launch ----------------------------------------------------
extern "C" void kernel_launch(void* const* d_in, const int* in_sizes, int n_in,
                              void* d_out, int out_size) {
    const float* x   = (const float*)d_in[0];   // [T,B,I]
    const float* Win = (const float*)d_in[1];   // [4H,I]
    const float* Whh = (const float*)d_in[2];   // [4H,H]
    float* out = (float*)d_out;

    const int smem_bytes = (ROWS * HH + BB * HH + 2 * 4 * 32) * (int)sizeof(float);
    cudaFuncSetAttribute(lstm_rec, cudaFuncAttributeMaxDynamicSharedMemorySize, smem_bytes);

    gemm_pre<<<dim3(GG / GBN, (TT * BB) / GBM), 256>>>(x, Win);
    lstm_rec<<<NBLK, RTH, smem_bytes>>>(Whh, out);
}

// round 8
// speedup vs baseline: 1.2270x; 1.2270x over previous
#include <cuda_runtime.h>
#include <math.h>

// Problem constants
#define TT 2048
#define BB 4
#define II 1024
#define HH 1024
#define GG (4 * HH)  // 4096 gate rows

// ---------------- scratch (static device globals; no allocations) ----------
__device__ float g_pre[(size_t)TT * BB * GG];  // [8192][4096] x@W_in^T (128 MB)
__device__ float g_h[2][BB * HH];              // double-buffered hidden state
__device__ unsigned g_bar;                     // single barrier counter (R1/R4-proven)

// packed fp32x2 FMA: d.lo += a.lo*b.lo ; d.hi += a.hi*b.hi (sm_100+)
__device__ __forceinline__ void ffma2(unsigned long long& d, unsigned long long a,
                                      unsigned long long b) {
    asm("fma.rn.f32x2 %0, %1, %2, %0;" : "+l"(d) : "l"(a), "l"(b));
}
__device__ __forceinline__ float ull_lo(unsigned long long v) {
    return __uint_as_float((unsigned)v);
}
__device__ __forceinline__ float ull_hi(unsigned long long v) {
    return __uint_as_float((unsigned)(v >> 32));
}
__device__ __forceinline__ float tanh_fast(float x) {
    float r;
    asm("tanh.approx.f32 %0, %1;" : "=f"(r) : "f"(x));
    return r;
}

// ---------------- kernel 1: pre = x @ W_in^T  (M=8192, N=4096, K=1024) ------
// fp32x2-packed tiled GEMM: BM=128, BN=128, BK=16, 256 threads, 8x8
// tile/thread. Block (0,0) also resets the recurrence scratch (replaces
// init_kernel; safe because lstm_rec runs in a later launch).
#define GBM 128
#define GBN 128
#define GBK 16

__global__ __launch_bounds__(256) void gemm_pre(const float* __restrict__ x,
                                                const float* __restrict__ Win) {
    __shared__ __align__(16) float As[GBK][GBM];
    __shared__ __align__(16) float Bs[GBK][GBN];
    const int tid = threadIdx.x;
    const int tx = tid & 15;        // 0..15  -> N (8 cols each)
    const int ty = tid >> 4;        // 0..15  -> M (8 rows each)
    const int mBase = blockIdx.y * GBM;
    const int nBase = blockIdx.x * GBN;

    // ---- inlined init (one block only): reset barrier + h0 = 0 ----
    if (blockIdx.x == 0 && blockIdx.y == 0) {
        if (tid == 0) g_bar = 0u;
#pragma unroll
        for (int i = 0; i < (2 * BB * HH) / 256; i++)
            ((float*)g_h)[i * 256 + tid] = 0.0f;
    }

    unsigned long long acc2[4][8];
#pragma unroll
    for (int i = 0; i < 4; i++)
#pragma unroll
        for (int j = 0; j < 8; j++) acc2[i][j] = 0ull;

    for (int k0 = 0; k0 < II; k0 += GBK) {
#pragma unroll
        for (int q = 0; q < 2; q++) {
            int id = tid * 2 + q;               // 0..511
            int m = id >> 2;
            int k4 = (id & 3) * 4;
            float4 v = *(const float4*)&x[(size_t)(mBase + m) * II + k0 + k4];
            As[k4 + 0][m] = v.x;
            As[k4 + 1][m] = v.y;
            As[k4 + 2][m] = v.z;
            As[k4 + 3][m] = v.w;
        }
#pragma unroll
        for (int q = 0; q < 2; q++) {
            int id = tid * 2 + q;               // 0..511
            int n = id >> 2;
            int k4 = (id & 3) * 4;
            float4 v = *(const float4*)&Win[(size_t)(nBase + n) * II + k0 + k4];
            Bs[k4 + 0][n] = v.x;
            Bs[k4 + 1][n] = v.y;
            Bs[k4 + 2][n] = v.z;
            Bs[k4 + 3][n] = v.w;
        }
        __syncthreads();

#pragma unroll
        for (int kk = 0; kk < GBK; kk++) {
            ulonglong2 t0 = *(const ulonglong2*)&As[kk][ty * 8];
            ulonglong2 t1 = *(const ulonglong2*)&As[kk][ty * 8 + 4];
            unsigned long long a2[4] = {t0.x, t0.y, t1.x, t1.y};
            float bq[8];
            *(float4*)&bq[0] = *(const float4*)&Bs[kk][tx * 8];
            *(float4*)&bq[4] = *(const float4*)&Bs[kk][tx * 8 + 4];
            unsigned long long bd[8];
#pragma unroll
            for (int j = 0; j < 8; j++) {
                unsigned bu = __float_as_uint(bq[j]);
                asm("mov.b64 %0, {%1, %1};" : "=l"(bd[j]) : "r"(bu));
            }
#pragma unroll
            for (int i = 0; i < 4; i++)
#pragma unroll
                for (int j = 0; j < 8; j++) ffma2(acc2[i][j], a2[i], bd[j]);
        }
        __syncthreads();
    }

#pragma unroll
    for (int i = 0; i < 4; i++) {
#pragma unroll
        for (int half = 0; half < 2; half++) {
            float4 vlo = make_float4(ull_lo(acc2[i][half * 4 + 0]), ull_lo(acc2[i][half * 4 + 1]),
                                     ull_lo(acc2[i][half * 4 + 2]), ull_lo(acc2[i][half * 4 + 3]));
            float4 vhi = make_float4(ull_hi(acc2[i][half * 4 + 0]), ull_hi(acc2[i][half * 4 + 1]),
                                     ull_hi(acc2[i][half * 4 + 2]), ull_hi(acc2[i][half * 4 + 3]));
            *(float4*)&g_pre[(size_t)(mBase + ty * 8 + 2 * i + 0) * GG + nBase + tx * 8 + half * 4] = vlo;
            *(float4*)&g_pre[(size_t)(mBase + ty * 8 + 2 * i + 1) * GG + nBase + tx * 8 + half * 4] = vhi;
        }
    }
}

// ---------------- kernel 2: persistent recurrence ---------------------------
// 128 CTAs x 512 threads (16 warps; 1 CTA/SM forced by 146 KB smem). CTA owns
// 8 hidden units (32 gate rows, 128 KB). Warp w: gate = w>>2, K-quarter = w&3;
// computes 8 rows x 4 batches over K=256 with packed FFMA2, register
// transpose-reduce, warp-0 cell update summing 4 K-quarter partials
// (c-state in warp-0 registers, fast tanh). Grid sync = single-counter atomic
// barrier + volatile poll (R1/R4-proven).
#define NBLK 128
#define UPB 8
#define ROWS 32
#define RTH 512

__global__ __launch_bounds__(RTH) void lstm_rec(const float* __restrict__ Whh,
                                                float* __restrict__ out) {
    extern __shared__ float sm[];
    float* W_s = sm;                          // [32][1024] 128 KB
    float* h_s = W_s + ROWS * HH;             // [4][1024]   16 KB
    float* part_s = h_s + BB * HH;            // [4 quarter][4 gate][32]  2 KB

    const int tid = threadIdx.x;
    const int blk = blockIdx.x;
    const int warp = tid >> 5;
    const int lane = tid & 31;
    const int gate = warp >> 2;               // 0..3
    const int q = warp & 3;                   // K-quarter 0..3

    // Stage W: local row r = gate*8 + u  <-  Whh[gate*1024 + blk*8 + u]
    for (int id = tid; id < ROWS * (HH / 4); id += RTH) {
        int r = id / (HH / 4);
        int c4 = id % (HH / 4);
        int g = r >> 3, ul = r & 7;
        ((float4*)&W_s[r * HH])[c4] =
            ((const float4*)&Whh[(size_t)(g * HH + blk * UPB + ul) * HH])[c4];
    }
    __syncthreads();

    // warp0 persistent cell state: lane = u*4 + b
    const int u = lane >> 2, b = lane & 3;
    const int ug = blk * UPB + u;
    float c_val = 0.0f;

    const float* Wbase = &W_s[gate * UPB * HH + q * (HH / 4)];
    const float* hbase = &h_s[q * (HH / 4)];

    for (int t = 0; t < TT; t++) {
        // Prefetch this step's pre-activations (consumed ~1500 cyc later).
        float pre_r[4];
        if (warp == 0) {
#pragma unroll
            for (int g = 0; g < 4; g++)
                pre_r[g] = __ldcs(&g_pre[(size_t)(t * BB + b) * GG + g * HH + ug]);
        }

        // Stage h_t (buffer t&1) into smem; __ldcg bypasses stale L1.
        const float4* hsrc = (const float4*)g_h[t & 1];
#pragma unroll
        for (int i = 0; i < (BB * HH) / 4 / RTH; i++)
            ((float4*)h_s)[i * RTH + tid] = __ldcg(&hsrc[i * RTH + tid]);
        __syncthreads();

        // GEMV: 8 rows x 4 batches over K=256 (2 iterations of 128).
        unsigned long long acc[8][4];
#pragma unroll
        for (int j = 0; j < 8; j++)
#pragma unroll
            for (int bb = 0; bb < 4; bb++) acc[j][bb] = 0ull;

#pragma unroll
        for (int it = 0; it < 2; it++) {
            const int base = it * 128 + lane * 4;
            ulonglong2 hv[4];
#pragma unroll
            for (int bb = 0; bb < 4; bb++)
                hv[bb] = *(const ulonglong2*)&hbase[bb * HH + base];
#pragma unroll
            for (int j = 0; j < 8; j++) {
                ulonglong2 wv = *(const ulonglong2*)&Wbase[j * HH + base];
#pragma unroll
                for (int bb = 0; bb < 4; bb++) {
                    ffma2(acc[j][bb], wv.x, hv[bb].x);
                    ffma2(acc[j][bb], wv.y, hv[bb].y);
                }
            }
        }

        // Collapse packed accumulators -> 32 scalars (index = j*4 + bb = u*4+b)
        float a[32];
#pragma unroll
        for (int j = 0; j < 8; j++)
#pragma unroll
            for (int bb = 0; bb < 4; bb++)
                a[j * 4 + bb] = ull_lo(acc[j][bb]) + ull_hi(acc[j][bb]);

        // Register transpose-reduce: lane l ends with full sum of index l.
#pragma unroll
        for (int s = 16; s >= 1; s >>= 1) {
            const bool up = (lane & s) != 0;
#pragma unroll
            for (int k = 0; k < s; k++) {
                float sendv = up ? a[k] : a[k + s];
                float keepv = up ? a[k + s] : a[k];
                float got = __shfl_xor_sync(0xFFFFFFFFu, sendv, s);
                a[k] = keepv + got;
            }
        }
        part_s[(q * 4 + gate) * 32 + lane] = a[0];
        __syncthreads();

        // Cell update: warp 0, lane = u*4 + b. Sum the 4 K-quarter partials.
        if (tid < 32) {
            float gsum[4];
#pragma unroll
            for (int g = 0; g < 4; g++) {
                gsum[g] = pre_r[g];
#pragma unroll
                for (int qq = 0; qq < 4; qq++)
                    gsum[g] += part_s[(qq * 4 + g) * 32 + lane];
            }
            float i_s = 1.0f / (1.0f + __expf(-gsum[0]));
            float f_s = 1.0f / (1.0f + __expf(-gsum[1]));
            float g_t = tanh_fast(gsum[2]);
            float o_s = 1.0f / (1.0f + __expf(-gsum[3]));
            c_val = f_s * c_val + i_s * g_t;
            float h = o_s * tanh_fast(c_val);
            g_h[(t + 1) & 1][b * HH + ug] = h;                      // next step input
            out[(size_t)(t * BB + b) * HH + ug] = h;                // layer output
            if (t == TT - 1) {
                out[(size_t)TT * BB * HH + b * HH + ug] = h;            // h_T
                out[(size_t)TT * BB * HH + BB * HH + b * HH + ug] = c_val;  // c_T
            }
            __syncwarp();
            if (lane == 0) {
                __threadfence();  // cumulative: orders warp-0's h stores (via syncwarp)
                atomicAdd(&g_bar, 1u);
                const unsigned target = (unsigned)(t + 1) * NBLK;
                while (*((volatile unsigned*)&g_bar) < target) {
                }
            }
        }
        __syncthreads();
    }
}

// ---------------- launch ----------------------------------------------------
extern "C" void kernel_launch(void* const* d_in, const int* in_sizes, int n_in,
                              void* d_out, int out_size) {
    const float* x   = (const float*)d_in[0];   // [T,B,I]
    const float* Win = (const float*)d_in[1];   // [4H,I]
    const float* Whh = (const float*)d_in[2];   // [4H,H]
    float* out = (float*)d_out;

    const int smem_bytes = (ROWS * HH + BB * HH + 4 * 4 * 32) * (int)sizeof(float);
    cudaFuncSetAttribute(lstm_rec, cudaFuncAttributeMaxDynamicSharedMemorySize, smem_bytes);

    gemm_pre<<<dim3(GG / GBN, (TT * BB) / GBM), 256>>>(x, Win);
    lstm_rec<<<NBLK, RTH, smem_bytes>>>(Whh, out);
}

// round 12
// speedup vs baseline: 1.2610x; 1.0277x over previous
#include <cuda_runtime.h>
#include <math.h>

// Problem constants
#define TT 2048
#define BB 4
#define II 1024
#define HH 1024
#define GG (4 * HH)  // 4096 gate rows

// ---------------- scratch (static device globals; no allocations) ----------
__device__ float g_pre[(size_t)TT * BB * GG];  // [8192][4096] x@W_in^T (128 MB)
__device__ float g_h[2][BB * HH];              // double-buffered hidden state
__device__ unsigned g_bar;                     // single barrier counter (proven)

// packed fp32x2 FMA: d.lo += a.lo*b.lo ; d.hi += a.hi*b.hi (sm_100+)
__device__ __forceinline__ void ffma2(unsigned long long& d, unsigned long long a,
                                      unsigned long long b) {
    asm("fma.rn.f32x2 %0, %1, %2, %0;" : "+l"(d) : "l"(a), "l"(b));
}
__device__ __forceinline__ float ull_lo(unsigned long long v) {
    return __uint_as_float((unsigned)v);
}
__device__ __forceinline__ float ull_hi(unsigned long long v) {
    return __uint_as_float((unsigned)(v >> 32));
}
__device__ __forceinline__ float tanh_fast(float x) {
    float r;
    asm("tanh.approx.f32 %0, %1;" : "=f"(r) : "f"(x));
    return r;
}
// sigma(x) = 0.5*tanh(x/2) + 0.5  (1 MUFU + 2 FMA vs exp+add+rcp chain)
__device__ __forceinline__ float sig_fast(float x) {
    return fmaf(tanh_fast(0.5f * x), 0.5f, 0.5f);
}

// ---------------- kernel 1: pre = x @ W_in^T  (M=8192, N=4096, K=1024) ------
// fp32x2-packed tiled GEMM: BM=128, BN=128, BK=16, 256 threads, 8x8
// tile/thread. Block (0,0) also resets the recurrence scratch.
#define GBM 128
#define GBN 128
#define GBK 16

__global__ __launch_bounds__(256) void gemm_pre(const float* __restrict__ x,
                                                const float* __restrict__ Win) {
    __shared__ __align__(16) float As[GBK][GBM];
    __shared__ __align__(16) float Bs[GBK][GBN];
    const int tid = threadIdx.x;
    const int tx = tid & 15;        // 0..15  -> N (8 cols each)
    const int ty = tid >> 4;        // 0..15  -> M (8 rows each)
    const int mBase = blockIdx.y * GBM;
    const int nBase = blockIdx.x * GBN;

    // ---- inlined init (one block only): reset barrier + h0 = 0 ----
    if (blockIdx.x == 0 && blockIdx.y == 0) {
        if (tid == 0) g_bar = 0u;
#pragma unroll
        for (int i = 0; i < (2 * BB * HH) / 256; i++)
            ((float*)g_h)[i * 256 + tid] = 0.0f;
    }

    unsigned long long acc2[4][8];
#pragma unroll
    for (int i = 0; i < 4; i++)
#pragma unroll
        for (int j = 0; j < 8; j++) acc2[i][j] = 0ull;

    for (int k0 = 0; k0 < II; k0 += GBK) {
#pragma unroll
        for (int q = 0; q < 2; q++) {
            int id = tid * 2 + q;               // 0..511
            int m = id >> 2;
            int k4 = (id & 3) * 4;
            float4 v = *(const float4*)&x[(size_t)(mBase + m) * II + k0 + k4];
            As[k4 + 0][m] = v.x;
            As[k4 + 1][m] = v.y;
            As[k4 + 2][m] = v.z;
            As[k4 + 3][m] = v.w;
        }
#pragma unroll
        for (int q = 0; q < 2; q++) {
            int id = tid * 2 + q;               // 0..511
            int n = id >> 2;
            int k4 = (id & 3) * 4;
            float4 v = *(const float4*)&Win[(size_t)(nBase + n) * II + k0 + k4];
            Bs[k4 + 0][n] = v.x;
            Bs[k4 + 1][n] = v.y;
            Bs[k4 + 2][n] = v.z;
            Bs[k4 + 3][n] = v.w;
        }
        __syncthreads();

#pragma unroll
        for (int kk = 0; kk < GBK; kk++) {
            ulonglong2 t0 = *(const ulonglong2*)&As[kk][ty * 8];
            ulonglong2 t1 = *(const ulonglong2*)&As[kk][ty * 8 + 4];
            unsigned long long a2[4] = {t0.x, t0.y, t1.x, t1.y};
            float bq[8];
            *(float4*)&bq[0] = *(const float4*)&Bs[kk][tx * 8];
            *(float4*)&bq[4] = *(const float4*)&Bs[kk][tx * 8 + 4];
            unsigned long long bd[8];
#pragma unroll
            for (int j = 0; j < 8; j++) {
                unsigned bu = __float_as_uint(bq[j]);
                asm("mov.b64 %0, {%1, %1};" : "=l"(bd[j]) : "r"(bu));
            }
#pragma unroll
            for (int i = 0; i < 4; i++)
#pragma unroll
                for (int j = 0; j < 8; j++) ffma2(acc2[i][j], a2[i], bd[j]);
        }
        __syncthreads();
    }

#pragma unroll
    for (int i = 0; i < 4; i++) {
#pragma unroll
        for (int half = 0; half < 2; half++) {
            float4 vlo = make_float4(ull_lo(acc2[i][half * 4 + 0]), ull_lo(acc2[i][half * 4 + 1]),
                                     ull_lo(acc2[i][half * 4 + 2]), ull_lo(acc2[i][half * 4 + 3]));
            float4 vhi = make_float4(ull_hi(acc2[i][half * 4 + 0]), ull_hi(acc2[i][half * 4 + 1]),
                                     ull_hi(acc2[i][half * 4 + 2]), ull_hi(acc2[i][half * 4 + 3]));
            *(float4*)&g_pre[(size_t)(mBase + ty * 8 + 2 * i + 0) * GG + nBase + tx * 8 + half * 4] = vlo;
            *(float4*)&g_pre[(size_t)(mBase + ty * 8 + 2 * i + 1) * GG + nBase + tx * 8 + half * 4] = vhi;
        }
    }
}

// ---------------- kernel 2: persistent recurrence ---------------------------
// 128 CTAs x 512 threads (16 warps; 1 CTA/SM via 130 KB smem). CTA owns 8
// hidden units (32 gate rows, 128 KB smem). Warp w: gate = w>>2, K-quarter
// = w&3; 8 rows x 4 batches over K=256 with packed FFMA2. h is loaded straight
// L2 -> registers per warp (lane-private K slices; no smem staging, no staging
// sync). Shfl transpose-reduce (R8-proven); warp-0 cell update sums the 4
// K-quarter partials; c-state in registers; fast tanh/sigmoid. Grid sync =
// single-counter atomic barrier + volatile poll.
#define NBLK 128
#define UPB 8
#define ROWS 32
#define RTH 512

__global__ __launch_bounds__(RTH) void lstm_rec(const float* __restrict__ Whh,
                                                float* __restrict__ out) {
    extern __shared__ float sm[];
    float* W_s = sm;                          // [32][1024] 128 KB
    float* part_s = W_s + ROWS * HH;          // [4 quarter][4 gate][32]  2 KB

    const int tid = threadIdx.x;
    const int blk = blockIdx.x;
    const int warp = tid >> 5;
    const int lane = tid & 31;
    const int gate = warp >> 2;               // 0..3
    const int q = warp & 3;                   // K-quarter 0..3

    // Stage W: local row r = gate*8 + u  <-  Whh[gate*1024 + blk*8 + u]
    for (int id = tid; id < ROWS * (HH / 4); id += RTH) {
        int r = id / (HH / 4);
        int c4 = id % (HH / 4);
        int g = r >> 3, ul = r & 7;
        ((float4*)&W_s[r * HH])[c4] =
            ((const float4*)&Whh[(size_t)(g * HH + blk * UPB + ul) * HH])[c4];
    }
    __syncthreads();

    // warp0 persistent cell state: lane = u*4 + b
    const int u = lane >> 2, b = lane & 3;
    const int ug = blk * UPB + u;
    float c_val = 0.0f;

    const float* Wbase = &W_s[gate * UPB * HH + q * (HH / 4)];
    const int hoff = q * (HH / 4) + lane * 4;  // this lane's K slice base

    for (int t = 0; t < TT; t++) {
        // Prefetch this step's pre-activations (consumed ~1500 cyc later).
        float pre_r[4];
        if (warp == 0) {
#pragma unroll
            for (int g = 0; g < 4; g++)
                pre_r[g] = __ldcs(&g_pre[(size_t)(t * BB + b) * GG + g * HH + ug]);
        }

        // h: L2 -> registers, lane-private slices (issue all 8 LDG.128 up
        // front; latency overlapped by the 16-warp mix and the W LDS stream).
        const float* hg = g_h[t & 1];
        ulonglong2 hv[2][4];
#pragma unroll
        for (int it = 0; it < 2; it++)
#pragma unroll
            for (int bb = 0; bb < 4; bb++)
                hv[it][bb] = __ldcg((const ulonglong2*)&hg[bb * HH + hoff + it * 128]);

        // GEMV: 8 rows x 4 batches over K=256 (2 iterations of 128).
        unsigned long long acc[8][4];
#pragma unroll
        for (int j = 0; j < 8; j++)
#pragma unroll
            for (int bb = 0; bb < 4; bb++) acc[j][bb] = 0ull;

#pragma unroll
        for (int it = 0; it < 2; it++) {
            const int base = it * 128 + lane * 4;
#pragma unroll
            for (int j = 0; j < 8; j++) {
                ulonglong2 wv = *(const ulonglong2*)&Wbase[j * HH + base];
#pragma unroll
                for (int bb = 0; bb < 4; bb++) {
                    ffma2(acc[j][bb], wv.x, hv[it][bb].x);
                    ffma2(acc[j][bb], wv.y, hv[it][bb].y);
                }
            }
        }

        // Collapse packed accumulators -> 32 scalars (index = j*4 + bb = u*4+b)
        float a[32];
#pragma unroll
        for (int j = 0; j < 8; j++)
#pragma unroll
            for (int bb = 0; bb < 4; bb++)
                a[j * 4 + bb] = ull_lo(acc[j][bb]) + ull_hi(acc[j][bb]);

        // Register transpose-reduce: lane l ends with full sum of index l.
#pragma unroll
        for (int s = 16; s >= 1; s >>= 1) {
            const bool up = (lane & s) != 0;
#pragma unroll
            for (int k = 0; k < s; k++) {
                float sendv = up ? a[k] : a[k + s];
                float keepv = up ? a[k + s] : a[k];
                float got = __shfl_xor_sync(0xFFFFFFFFu, sendv, s);
                a[k] = keepv + got;
            }
        }
        part_s[(q * 4 + gate) * 32 + lane] = a[0];
        __syncthreads();

        // Cell update: warp 0, lane = u*4 + b. Sum the 4 K-quarter partials.
        if (tid < 32) {
            float gsum[4];
#pragma unroll
            for (int g = 0; g < 4; g++) {
                gsum[g] = pre_r[g];
#pragma unroll
                for (int qq = 0; qq < 4; qq++)
                    gsum[g] += part_s[(qq * 4 + g) * 32 + lane];
            }
            float i_s = sig_fast(gsum[0]);
            float f_s = sig_fast(gsum[1]);
            float g_t = tanh_fast(gsum[2]);
            float o_s = sig_fast(gsum[3]);
            c_val = f_s * c_val + i_s * g_t;
            float h = o_s * tanh_fast(c_val);
            g_h[(t + 1) & 1][b * HH + ug] = h;                      // next step input
            out[(size_t)(t * BB + b) * HH + ug] = h;                // layer output
            if (t == TT - 1) {
                out[(size_t)TT * BB * HH + b * HH + ug] = h;            // h_T
                out[(size_t)TT * BB * HH + BB * HH + b * HH + ug] = c_val;  // c_T
            }
            __syncwarp();
            if (lane == 0) {
                __threadfence();  // cumulative: orders warp-0's h stores (via syncwarp)
                atomicAdd(&g_bar, 1u);
                const unsigned target = (unsigned)(t + 1) * NBLK;
                while (*((volatile unsigned*)&g_bar) < target) {
                }
            }
        }
        __syncthreads();
    }
}

// ---------------- launch ----------------------------------------------------
extern "C" void kernel_launch(void* const* d_in, const int* in_sizes, int n_in,
                              void* d_out, int out_size) {
    const float* x   = (const float*)d_in[0];   // [T,B,I]
    const float* Win = (const float*)d_in[1];   // [4H,I]
    const float* Whh = (const float*)d_in[2];   // [4H,H]
    float* out = (float*)d_out;

    const int smem_bytes = (ROWS * HH + 4 * 4 * 32) * (int)sizeof(float);
    cudaFuncSetAttribute(lstm_rec, cudaFuncAttributeMaxDynamicSharedMemorySize, smem_bytes);

    gemm_pre<<<dim3(GG / GBN, (TT * BB) / GBM), 256>>>(x, Win);
    lstm_rec<<<NBLK, RTH, smem_bytes>>>(Whh, out);
}